// round 1
// baseline (speedup 1.0000x reference)
#include <cuda_runtime.h>

// ---------------------------------------------------------------------------
// RestorationLoss: 1 - SSIM(x,y) + MSE(x,y)
// SSIM: 11x11 Gaussian (sigma=1.5) depthwise conv, SAME zero padding.
//
// Key transforms:
//   * separable Gaussian (11+11 taps)
//   * convolve only 4 fields of s=x+y, d=x-y:  {s, d, s^2, d^2}
//       mu1*mu2        = (mus^2 - mud^2)/4
//       mu1^2+mu2^2    = (mus^2 + mud^2)/2
//       sigma12        = (Ess - Edd)/4 - mu1*mu2
//       sig1^2+sig2^2  = (Ess + Edd)/2 - (mu1^2+mu2^2)
//   * MSE = mean(d^2)
// ---------------------------------------------------------------------------

#define IMG      512
#define TW       32
#define TH       32
#define HALO     5
#define LW       (TW + 2*HALO)   // 42
#define LH       (TH + 2*HALO)   // 42
#define SSTRIDE  44              // raw tile row stride (floats)
#define HSTRIDE  33              // h-buffer row stride (floats)
#define NPLANES  48              // 16*3
#define TILES_X  (IMG/TW)        // 16
#define TILES_Y  (IMG/TH)        // 16
#define NBLOCKS  (NPLANES*TILES_X*TILES_Y)  // 12288
#define NPIX     (16.0*3.0*512.0*512.0)

#define C1 1.0e-4f
#define C2 9.0e-4f

// normalized 1D gaussian, sigma=1.5, K=11 (indices -5..5)
static __device__ constexpr float GW[11] = {
    0.00102838f, 0.00759876f, 0.03600077f, 0.10936069f, 0.21300554f,
    0.26601172f,
    0.21300554f, 0.10936069f, 0.03600077f, 0.00759876f, 0.00102838f
};

__device__ float g_ssim_part[NBLOCKS];
__device__ float g_mse_part[NBLOCKS];

__global__ __launch_bounds__(256)
void ssim_tile_kernel(const float* __restrict__ x, const float* __restrict__ y)
{
    __shared__ float s_s[LH][SSTRIDE];
    __shared__ float s_d[LH][SSTRIDE];
    __shared__ float s_h[4][LH][HSTRIDE];   // hs, hd, hss, hdd
    __shared__ float red_s[8], red_m[8];

    const int tid   = threadIdx.x;
    const int plane = blockIdx.z;
    const int r0    = blockIdx.y * TH - HALO;
    const int c0    = blockIdx.x * TW - HALO;

    const float* __restrict__ xp = x + (size_t)plane * (IMG * IMG);
    const float* __restrict__ yp = y + (size_t)plane * (IMG * IMG);

    // ---- load raw tile with halo, form s = x+y, d = x-y (zero pad) ----
    for (int i = tid; i < LH * LW; i += 256) {
        int lr = i / LW;
        int lc = i - lr * LW;
        int gr = r0 + lr;
        int gc = c0 + lc;
        float xv = 0.f, yv = 0.f;
        if ((unsigned)gr < IMG && (unsigned)gc < IMG) {
            int gi = gr * IMG + gc;
            xv = __ldg(xp + gi);
            yv = __ldg(yp + gi);
        }
        s_s[lr][lc] = xv + yv;
        s_d[lr][lc] = xv - yv;
    }
    __syncthreads();

    // ---- horizontal pass: 42 rows x 32 cols, squares formed in-flight ----
    for (int i = tid; i < LH * TW; i += 256) {
        int r = i >> 5;
        int c = i & 31;
        float hs = 0.f, hd = 0.f, hss = 0.f, hdd = 0.f;
        #pragma unroll
        for (int j = 0; j < 11; j++) {
            float sv = s_s[r][c + j];
            float dv = s_d[r][c + j];
            float ts = GW[j] * sv;
            float td = GW[j] * dv;
            hs += ts;
            hd += td;
            hss = fmaf(ts, sv, hss);
            hdd = fmaf(td, dv, hdd);
        }
        s_h[0][r][c] = hs;
        s_h[1][r][c] = hd;
        s_h[2][r][c] = hss;
        s_h[3][r][c] = hdd;
    }
    __syncthreads();

    // ---- vertical pass: each thread = 1 column, 4 consecutive rows ----
    const int c  = tid & 31;
    const int rb = (tid >> 5) * 4;      // 0,4,...,28

    float a_s[4]  = {0.f, 0.f, 0.f, 0.f};
    float a_d[4]  = {0.f, 0.f, 0.f, 0.f};
    float a_ss[4] = {0.f, 0.f, 0.f, 0.f};
    float a_dd[4] = {0.f, 0.f, 0.f, 0.f};

    #pragma unroll
    for (int j = 0; j < 14; j++) {
        int r = rb + j;
        float vs  = s_h[0][r][c];
        float vd  = s_h[1][r][c];
        float vss = s_h[2][r][c];
        float vdd = s_h[3][r][c];
        #pragma unroll
        for (int o = 0; o < 4; o++) {
            int k = j - o;
            if (k >= 0 && k <= 10) {
                a_s[o]  = fmaf(GW[k], vs,  a_s[o]);
                a_d[o]  = fmaf(GW[k], vd,  a_d[o]);
                a_ss[o] = fmaf(GW[k], vss, a_ss[o]);
                a_dd[o] = fmaf(GW[k], vdd, a_dd[o]);
            }
        }
    }

    float ssim_acc = 0.f;
    float mse_acc  = 0.f;
    #pragma unroll
    for (int o = 0; o < 4; o++) {
        float mus = a_s[o], mud = a_d[o];
        float ess = a_ss[o], edd = a_dd[o];
        float mus2 = mus * mus;
        float mud2 = mud * mud;
        float mu12   = 0.25f * (mus2 - mud2);          // mu1*mu2
        float musum  = 0.5f  * (mus2 + mud2);          // mu1^2+mu2^2
        float sig12  = 0.25f * (ess - edd) - mu12;     // sigma12
        float sigsum = 0.5f  * (ess + edd) - musum;    // sigma1^2+sigma2^2
        float num = (2.f * mu12 + C1) * (2.f * sig12 + C2);
        float den = (musum + C1) * (sigsum + C2);
        ssim_acc += __fdividef(num, den);
        float dv = s_d[rb + o + HALO][c + HALO];
        mse_acc  = fmaf(dv, dv, mse_acc);
    }

    // ---- block reduction ----
    #pragma unroll
    for (int off = 16; off > 0; off >>= 1) {
        ssim_acc += __shfl_down_sync(0xffffffffu, ssim_acc, off);
        mse_acc  += __shfl_down_sync(0xffffffffu, mse_acc,  off);
    }
    if ((tid & 31) == 0) {
        red_s[tid >> 5] = ssim_acc;
        red_m[tid >> 5] = mse_acc;
    }
    __syncthreads();
    if (tid == 0) {
        float ss = 0.f, mm = 0.f;
        #pragma unroll
        for (int w = 0; w < 8; w++) { ss += red_s[w]; mm += red_m[w]; }
        int bid = (blockIdx.z * gridDim.y + blockIdx.y) * gridDim.x + blockIdx.x;
        g_ssim_part[bid] = ss;
        g_mse_part[bid]  = mm;
    }
}

__global__ __launch_bounds__(256)
void finalize_kernel(float* __restrict__ out)
{
    __shared__ double rs[256], rm[256];
    int tid = threadIdx.x;
    double ss = 0.0, mm = 0.0;
    for (int i = tid; i < NBLOCKS; i += 256) {
        ss += (double)g_ssim_part[i];
        mm += (double)g_mse_part[i];
    }
    rs[tid] = ss;
    rm[tid] = mm;
    __syncthreads();
    for (int s = 128; s > 0; s >>= 1) {
        if (tid < s) { rs[tid] += rs[tid + s]; rm[tid] += rm[tid + s]; }
        __syncthreads();
    }
    if (tid == 0) {
        double inv_n = 1.0 / NPIX;
        out[0] = (float)(1.0 - rs[0] * inv_n + rm[0] * inv_n);
    }
}

extern "C" void kernel_launch(void* const* d_in, const int* in_sizes, int n_in,
                              void* d_out, int out_size)
{
    const float* x = (const float*)d_in[0];
    const float* y = (const float*)d_in[1];
    float* out = (float*)d_out;

    dim3 grid(TILES_X, TILES_Y, NPLANES);
    ssim_tile_kernel<<<grid, 256>>>(x, y);
    finalize_kernel<<<1, 256>>>(out);
}

// round 2
// speedup vs baseline: 1.0193x; 1.0193x over previous
#include <cuda_runtime.h>

// ---------------------------------------------------------------------------
// RestorationLoss: 1 - SSIM(x,y) + MSE(x,y)
//   * separable 11-tap Gaussian, zero padding
//   * 4 convolved fields of s=x+y, d=x-y packed as f32x2: (s,d), (s^2,d^2)
//   * packed fma.rn.f32x2 (FFMA2) everywhere; LDS.64/STS.64 smem traffic
//   * 32x64 tiles, dynamic smem; deterministic fixed-point atomic reduction
// ---------------------------------------------------------------------------

#define IMG      512
#define TW       32
#define TH       64
#define HALO     5
#define LW       (TW + 2*HALO)   // 42
#define LH       (TH + 2*HALO)   // 74
#define SDSTR    45              // float2 stride of raw (s,d) tile
#define HSTR     33              // float2 stride of h-filtered buffers
#define NPIX     (16.0*3.0*512.0*512.0)
#define FXSCALE  268435456.0     // 2^28

#define C1 1.0e-4f
#define C2 9.0e-4f

typedef unsigned long long ull;

// normalized 1D gaussian, sigma=1.5, K=11
#define G0 0.00102838f
#define G1 0.00759876f
#define G2 0.03600077f
#define G3 0.10936069f
#define G4 0.21300554f
#define G5 0.26601172f

__constant__ float2 GW2[11] = {
    {G0,G0},{G1,G1},{G2,G2},{G3,G3},{G4,G4},{G5,G5},
    {G4,G4},{G3,G3},{G2,G2},{G1,G1},{G0,G0}
};

__device__ ull g_acc[2];   // [0]=ssim sum, [1]=mse sum, fixed point 2^28

static __device__ __forceinline__ ull fma2(ull a, ull b, ull c) {
    ull r; asm("fma.rn.f32x2 %0, %1, %2, %3;" : "=l"(r) : "l"(a), "l"(b), "l"(c));
    return r;
}
static __device__ __forceinline__ ull mul2(ull a, ull b) {
    ull r; asm("mul.rn.f32x2 %0, %1, %2;" : "=l"(r) : "l"(a), "l"(b));
    return r;
}
static __device__ __forceinline__ ull pack2(float lo, float hi) {
    ull r; asm("mov.b64 %0, {%1,%2};" : "=l"(r) : "f"(lo), "f"(hi));
    return r;
}
static __device__ __forceinline__ float2 unpack2(ull v) {
    float2 r; asm("mov.b64 {%0,%1}, %2;" : "=f"(r.x), "=f"(r.y) : "l"(v));
    return r;
}

__global__ __launch_bounds__(256)
void ssim_tile_kernel(const float* __restrict__ x, const float* __restrict__ y)
{
    extern __shared__ ull smem_u[];
    ull*   sd  = smem_u;                 // [LH][SDSTR] packed (s,d)
    ull*   h1  = sd + LH * SDSTR;        // [LH][HSTR]  packed (hs,hd)
    ull*   h2  = h1 + LH * HSTR;         // [LH][HSTR]  packed (hss,hdd)
    float* red = (float*)(h2 + LH * HSTR);  // 16 floats

    const int tid   = threadIdx.x;
    const int plane = blockIdx.z;
    const int r0    = blockIdx.y * TH - HALO;
    const int c0    = blockIdx.x * TW - HALO;

    const float* __restrict__ xp = x + (size_t)plane * (IMG * IMG);
    const float* __restrict__ yp = y + (size_t)plane * (IMG * IMG);

    // packed gaussian weights (thread-uniform -> UR / const cache)
    ull gw[11];
    #pragma unroll
    for (int k = 0; k < 11; k++) gw[k] = ((const ull*)GW2)[k];

    // ---- load raw tile with halo; MSE accumulated on the fly ----
    float mse_acc = 0.f;
    const bool fast = (r0 >= 0) & (r0 + LH <= IMG) & (c0 >= 0) & (c0 + LW <= IMG);
    if (fast) {
        for (int i = tid; i < LH * LW; i += 256) {
            int lr = i / LW;
            int lc = i - lr * LW;
            int gi = (r0 + lr) * IMG + (c0 + lc);
            float xv = __ldg(xp + gi);
            float yv = __ldg(yp + gi);
            float s = xv + yv, d = xv - yv;
            sd[lr * SDSTR + lc] = pack2(s, d);
            if ((unsigned)(lr - HALO) < TH && (unsigned)(lc - HALO) < TW)
                mse_acc = fmaf(d, d, mse_acc);
        }
    } else {
        for (int i = tid; i < LH * LW; i += 256) {
            int lr = i / LW;
            int lc = i - lr * LW;
            int gr = r0 + lr, gc = c0 + lc;
            float xv = 0.f, yv = 0.f;
            if ((unsigned)gr < IMG && (unsigned)gc < IMG) {
                int gi = gr * IMG + gc;
                xv = __ldg(xp + gi);
                yv = __ldg(yp + gi);
            }
            float s = xv + yv, d = xv - yv;
            sd[lr * SDSTR + lc] = pack2(s, d);
            if ((unsigned)(lr - HALO) < TH && (unsigned)(lc - HALO) < TW)
                mse_acc = fmaf(d, d, mse_acc);
        }
    }
    __syncthreads();

    // ---- horizontal pass: 4 consecutive outputs per thread from 14 loads ----
    for (int i = tid; i < LH * (TW / 4); i += 256) {   // 74*8 = 592 groups
        int r  = i >> 3;
        int cg = (i & 7) * 4;
        const ull* row = sd + r * SDSTR + cg;
        ull a1[4] = {0,0,0,0};
        ull a2[4] = {0,0,0,0};
        #pragma unroll
        for (int t = 0; t < 14; t++) {
            ull v  = row[t];
            ull v2 = mul2(v, v);
            #pragma unroll
            for (int o = 0; o < 4; o++) {
                int k = t - o;
                if (k >= 0 && k <= 10) {
                    a1[o] = fma2(v,  gw[k], a1[o]);
                    a2[o] = fma2(v2, gw[k], a2[o]);
                }
            }
        }
        #pragma unroll
        for (int o = 0; o < 4; o++) {
            h1[r * HSTR + cg + o] = a1[o];
            h2[r * HSTR + cg + o] = a2[o];
        }
    }
    __syncthreads();

    // ---- vertical pass: each thread = 1 column x 8 consecutive rows ----
    const int c  = tid & 31;
    const int rb = (tid >> 5) * 8;

    ull b1[8] = {0,0,0,0,0,0,0,0};
    ull b2[8] = {0,0,0,0,0,0,0,0};
    #pragma unroll
    for (int j = 0; j < 18; j++) {
        ull v1 = h1[(rb + j) * HSTR + c];
        ull v2 = h2[(rb + j) * HSTR + c];
        #pragma unroll
        for (int o = 0; o < 8; o++) {
            int k = j - o;
            if (k >= 0 && k <= 10) {
                b1[o] = fma2(v1, gw[k], b1[o]);
                b2[o] = fma2(v2, gw[k], b2[o]);
            }
        }
    }

    float ssim_acc = 0.f;
    #pragma unroll
    for (int o = 0; o < 8; o++) {
        float2 m = unpack2(b1[o]);   // (mu_s, mu_d)
        float2 e = unpack2(b2[o]);   // (E[s^2], E[d^2])
        float mus2 = m.x * m.x;
        float mud2 = m.y * m.y;
        float mu12   = 0.25f * (mus2 - mud2);       // mu1*mu2
        float musum  = 0.5f  * (mus2 + mud2);       // mu1^2+mu2^2
        float sig12  = 0.25f * (e.x - e.y) - mu12;  // sigma12
        float sigsum = 0.5f  * (e.x + e.y) - musum; // sigma1^2+sigma2^2
        float num = (2.f * mu12 + C1) * (2.f * sig12 + C2);
        float den = (musum + C1) * (sigsum + C2);
        ssim_acc += __fdividef(num, den);
    }

    // ---- block reduction -> deterministic fixed-point atomics ----
    #pragma unroll
    for (int off = 16; off > 0; off >>= 1) {
        ssim_acc += __shfl_down_sync(0xffffffffu, ssim_acc, off);
        mse_acc  += __shfl_down_sync(0xffffffffu, mse_acc,  off);
    }
    if ((tid & 31) == 0) {
        red[tid >> 5]     = ssim_acc;
        red[8 + (tid >> 5)] = mse_acc;
    }
    __syncthreads();
    if (tid < 2) {
        float sum = 0.f;
        #pragma unroll
        for (int w = 0; w < 8; w++) sum += red[tid * 8 + w];
        long long q = __double2ll_rn((double)sum * FXSCALE);
        atomicAdd(&g_acc[tid], (ull)q);
    }
}

__global__ void init_kernel()
{
    g_acc[0] = 0ull;
    g_acc[1] = 0ull;
}

__global__ void finalize_kernel(float* __restrict__ out)
{
    double inv = 1.0 / (NPIX * FXSCALE);
    double ss = (double)(long long)g_acc[0] * inv;
    double mm = (double)(long long)g_acc[1] * inv;
    out[0] = (float)(1.0 - ss + mm);
}

extern "C" void kernel_launch(void* const* d_in, const int* in_sizes, int n_in,
                              void* d_out, int out_size)
{
    const float* x = (const float*)d_in[0];
    const float* y = (const float*)d_in[1];
    float* out = (float*)d_out;

    const size_t smem_bytes = (LH * SDSTR + 2 * LH * HSTR) * sizeof(ull) + 64;
    cudaFuncSetAttribute(ssim_tile_kernel,
                         cudaFuncAttributeMaxDynamicSharedMemorySize,
                         (int)smem_bytes);

    init_kernel<<<1, 1>>>();
    dim3 grid(IMG / TW, IMG / TH, 48);   // (16, 8, 48)
    ssim_tile_kernel<<<grid, 256, smem_bytes>>>(x, y);
    finalize_kernel<<<1, 1>>>(out);
}

// round 3
// speedup vs baseline: 1.5107x; 1.4820x over previous
#include <cuda_runtime.h>

// ---------------------------------------------------------------------------
// RestorationLoss: 1 - SSIM(x,y) + MSE(x,y), single fused kernel.
//   * separable 11-tap Gaussian; fields (s,d),(s^2,d^2) packed f32x2 (FFMA2)
//   * h-pass reads GLOBAL directly (vector LDG.128), writes packed smem
//   * v-pass 8 outputs/thread; MSE folded into h-pass
//   * deterministic fixed-point atomic reduction, last-block finalize+reset
// ---------------------------------------------------------------------------

#define IMG     512
#define TW      32
#define TH      64
#define HALO    5
#define LH      (TH + 2*HALO)     // 74
#define HSTR    34                // ull stride of h buffers (even -> 16B stores ok)
#define NBX     (IMG/TW)          // 16
#define NBY     (IMG/TH)          // 8
#define NPL     48
#define NBLOCKS (NBX*NBY*NPL)     // 6144
#define NPIX    (16.0*3.0*512.0*512.0)
#define FXS     268435456.0       // 2^28

#define C1f 1.0e-4f
#define C2f 9.0e-4f

typedef unsigned long long ull;

// normalized 1D gaussian sigma=1.5, symmetric: only 6 unique packed weights
__constant__ float2 GW2[6] = {
    {0.00102838f, 0.00102838f},
    {0.00759876f, 0.00759876f},
    {0.03600077f, 0.03600077f},
    {0.10936069f, 0.10936069f},
    {0.21300554f, 0.21300554f},
    {0.26601172f, 0.26601172f}
};

__device__ ull g_acc[2] = {0ull, 0ull};   // [0]=ssim, [1]=mse, fixed point 2^28
__device__ unsigned g_count = 0u;

static __device__ __forceinline__ ull fma2(ull a, ull b, ull c) {
    ull r; asm("fma.rn.f32x2 %0, %1, %2, %3;" : "=l"(r) : "l"(a), "l"(b), "l"(c));
    return r;
}
static __device__ __forceinline__ ull mul2(ull a, ull b) {
    ull r; asm("mul.rn.f32x2 %0, %1, %2;" : "=l"(r) : "l"(a), "l"(b));
    return r;
}
static __device__ __forceinline__ ull pack2(float lo, float hi) {
    ull r; asm("mov.b64 %0, {%1,%2};" : "=l"(r) : "f"(lo), "f"(hi));
    return r;
}
static __device__ __forceinline__ float2 unpack2(ull v) {
    float2 r; asm("mov.b64 {%0,%1}, %2;" : "=f"(r.x), "=f"(r.y) : "l"(v));
    return r;
}

__global__ __launch_bounds__(256, 3)
void loss_kernel(const float* __restrict__ x, const float* __restrict__ y,
                 float* __restrict__ out)
{
    __shared__ ull  h1[LH * HSTR];
    __shared__ ull  h2[LH * HSTR];
    __shared__ float red[16];
    __shared__ int  s_last;

    const int tid   = threadIdx.x;
    const int bx    = blockIdx.x;
    const int by    = blockIdx.y;
    const int plane = blockIdx.z;
    const int base  = bx * TW;
    const int r0    = by * TH - HALO;

    const float* __restrict__ xp = x + (size_t)plane * (IMG * IMG);
    const float* __restrict__ yp = y + (size_t)plane * (IMG * IMG);

    ull gw[6];
    #pragma unroll
    for (int k = 0; k < 6; k++) gw[k] = ((const ull*)GW2)[k];
    #define WK(k) gw[(k) <= 5 ? (k) : 10 - (k)]

    const bool fast = (bx > 0) & (bx < NBX - 1) & (by > 0) & (by < NBY - 1);

    // ---- horizontal pass straight from global; MSE folded in ----
    float mse_acc = 0.f;
    for (int i = tid; i < LH * 8; i += 256) {        // 592 groups of 4 outputs
        const int r  = i >> 3;
        const int cg = (i & 7) * 4;
        const int gr = r0 + r;
        const bool mrow = (r >= HALO) & (r < HALO + TH);

        float vx[20], vy[20];
        if (fast) {
            const float4* xr = (const float4*)(xp + gr * IMG + base + cg - 8);
            const float4* yr = (const float4*)(yp + gr * IMG + base + cg - 8);
            #pragma unroll
            for (int q = 0; q < 5; q++) {
                float4 a = __ldg(xr + q);
                float4 b = __ldg(yr + q);
                vx[4*q+0] = a.x; vx[4*q+1] = a.y; vx[4*q+2] = a.z; vx[4*q+3] = a.w;
                vy[4*q+0] = b.x; vy[4*q+1] = b.y; vy[4*q+2] = b.z; vy[4*q+3] = b.w;
            }
        } else {
            #pragma unroll
            for (int v = 0; v < 20; v++) {
                int gc = base + cg - 8 + v;
                bool ok = ((unsigned)gr < IMG) & ((unsigned)gc < IMG);
                vx[v] = ok ? __ldg(xp + gr * IMG + gc) : 0.f;
                vy[v] = ok ? __ldg(yp + gr * IMG + gc) : 0.f;
            }
        }

        ull a1[4] = {0,0,0,0};
        ull a2[4] = {0,0,0,0};
        #pragma unroll
        for (int t = 0; t < 14; t++) {
            const int vi = t + 3;
            float s = vx[vi] + vy[vi];
            float d = vx[vi] - vy[vi];
            if (t >= 5 && t <= 8 && mrow)
                mse_acc = fmaf(d, d, mse_acc);
            ull v  = pack2(s, d);
            ull v2 = mul2(v, v);
            #pragma unroll
            for (int o = 0; o < 4; o++) {
                const int k = t - o;
                if (k >= 0 && k <= 10) {
                    a1[o] = fma2(v,  WK(k), a1[o]);
                    a2[o] = fma2(v2, WK(k), a2[o]);
                }
            }
        }
        #pragma unroll
        for (int o = 0; o < 4; o++) {
            h1[r * HSTR + cg + o] = a1[o];
            h2[r * HSTR + cg + o] = a2[o];
        }
    }
    __syncthreads();

    // ---- vertical pass: 1 column x 8 consecutive rows per thread ----
    const int c  = tid & 31;
    const int rb = (tid >> 5) * 8;

    ull b1[8] = {0,0,0,0,0,0,0,0};
    ull b2[8] = {0,0,0,0,0,0,0,0};
    #pragma unroll
    for (int j = 0; j < 18; j++) {
        ull u1 = h1[(rb + j) * HSTR + c];
        ull u2 = h2[(rb + j) * HSTR + c];
        #pragma unroll
        for (int o = 0; o < 8; o++) {
            const int k = j - o;
            if (k >= 0 && k <= 10) {
                b1[o] = fma2(u1, WK(k), b1[o]);
                b2[o] = fma2(u2, WK(k), b2[o]);
            }
        }
    }

    float ssim_acc = 0.f;
    #pragma unroll
    for (int o = 0; o < 8; o++) {
        float2 m = unpack2(b1[o]);   // (mu_s, mu_d)
        float2 e = unpack2(b2[o]);   // (E[s^2], E[d^2])
        float mus2 = m.x * m.x;
        float mud2 = m.y * m.y;
        float mu12   = 0.25f * (mus2 - mud2);
        float musum  = 0.5f  * (mus2 + mud2);
        float sig12  = 0.25f * (e.x - e.y) - mu12;
        float sigsum = 0.5f  * (e.x + e.y) - musum;
        float num = (2.f * mu12 + C1f) * (2.f * sig12 + C2f);
        float den = (musum + C1f) * (sigsum + C2f);
        ssim_acc += __fdividef(num, den);
    }

    // ---- block reduction -> deterministic fixed-point atomics ----
    #pragma unroll
    for (int off = 16; off > 0; off >>= 1) {
        ssim_acc += __shfl_down_sync(0xffffffffu, ssim_acc, off);
        mse_acc  += __shfl_down_sync(0xffffffffu, mse_acc,  off);
    }
    if ((tid & 31) == 0) {
        red[tid >> 5]       = ssim_acc;
        red[8 + (tid >> 5)] = mse_acc;
    }
    __syncthreads();
    if (tid == 0) {
        float ss = 0.f, mm = 0.f;
        #pragma unroll
        for (int w = 0; w < 8; w++) { ss += red[w]; mm += red[8 + w]; }
        atomicAdd(&g_acc[0], (ull)__double2ll_rn((double)ss * FXS));
        atomicAdd(&g_acc[1], (ull)__double2ll_rn((double)mm * FXS));
        __threadfence();
        unsigned t = atomicAdd(&g_count, 1u);
        s_last = (t == NBLOCKS - 1);
    }
    __syncthreads();

    // ---- last block finalizes and resets for the next graph replay ----
    if (s_last && tid == 0) {
        __threadfence();
        ull a0 = atomicExch(&g_acc[0], 0ull);
        ull a1v = atomicExch(&g_acc[1], 0ull);
        atomicExch(&g_count, 0u);
        double inv = 1.0 / (NPIX * FXS);
        double ss = (double)(long long)a0 * inv;
        double mm = (double)(long long)a1v * inv;
        out[0] = (float)(1.0 - ss + mm);
    }
}

extern "C" void kernel_launch(void* const* d_in, const int* in_sizes, int n_in,
                              void* d_out, int out_size)
{
    const float* x = (const float*)d_in[0];
    const float* y = (const float*)d_in[1];
    float* out = (float*)d_out;

    dim3 grid(NBX, NBY, NPL);   // (16, 8, 48) = 6144 blocks
    loss_kernel<<<grid, 256>>>(x, y, out);
}

// round 4
// speedup vs baseline: 1.6032x; 1.0612x over previous
#include <cuda_runtime.h>

// ---------------------------------------------------------------------------
// RestorationLoss: 1 - SSIM(x,y) + MSE(x,y), single fused kernel.
//   * separable 11-tap Gaussian; packed f32x2 fields (s,d),(s^2,d^2) (FFMA2)
//   * h-pass: 8 outputs/thread streamed from 12 predicated LDG.128
//   * interleaved h-buffer, conflict-free STS.128 / LDS.128
//   * v-pass: 7 outputs/thread; masked edge rows
//   * deterministic fixed-point atomic reduction + last-block finalize/reset
// ---------------------------------------------------------------------------

#define IMG     512
#define TW      32
#define TH      54
#define HALO    5
#define LH      64                 // h rows produced (TH + 2*HALO)
#define LHBUF   66                 // + 2 zero guard rows for masked v outputs
#define HSTR    66                 // ull row stride of interleaved h buffer
#define NBX     (IMG/TW)           // 16
#define NBY     10                 // ceil(512/54)
#define NPL     48
#define NBLOCKS (NBX*NBY*NPL)      // 7680
#define NPIX    (16.0*3.0*512.0*512.0)
#define FXS     268435456.0        // 2^28

#define C1f 1.0e-4f
#define C2f 9.0e-4f

typedef unsigned long long ull;

__constant__ float2 GW2[6] = {
    {0.00102838f, 0.00102838f},
    {0.00759876f, 0.00759876f},
    {0.03600077f, 0.03600077f},
    {0.10936069f, 0.10936069f},
    {0.21300554f, 0.21300554f},
    {0.26601172f, 0.26601172f}
};

__device__ ull g_acc[2] = {0ull, 0ull};
__device__ unsigned g_count = 0u;

static __device__ __forceinline__ ull fma2(ull a, ull b, ull c) {
    ull r; asm("fma.rn.f32x2 %0, %1, %2, %3;" : "=l"(r) : "l"(a), "l"(b), "l"(c));
    return r;
}
static __device__ __forceinline__ ull mul2(ull a, ull b) {
    ull r; asm("mul.rn.f32x2 %0, %1, %2;" : "=l"(r) : "l"(a), "l"(b));
    return r;
}
static __device__ __forceinline__ ull pack2(float lo, float hi) {
    ull r; asm("mov.b64 %0, {%1,%2};" : "=l"(r) : "f"(lo), "f"(hi));
    return r;
}
static __device__ __forceinline__ float2 unpack2(ull v) {
    float2 r; asm("mov.b64 {%0,%1}, %2;" : "=f"(r.x), "=f"(r.y) : "l"(v));
    return r;
}

__global__ __launch_bounds__(256, 3)
void loss_kernel(const float* __restrict__ x, const float* __restrict__ y,
                 float* __restrict__ out)
{
    __shared__ ull  h[LHBUF * HSTR];   // interleaved (u1,u2) pairs: col c -> 2c, 2c+1
    __shared__ float red[16];
    __shared__ int  s_last;

    const int tid   = threadIdx.x;
    const int bx    = blockIdx.x;
    const int by    = blockIdx.y;
    const int plane = blockIdx.z;
    const int base  = bx * TW;
    const int r0    = by * TH - HALO;

    const float* __restrict__ xp = x + (size_t)plane * (IMG * IMG);
    const float* __restrict__ yp = y + (size_t)plane * (IMG * IMG);

    ull gw[6];
    #pragma unroll
    for (int k = 0; k < 6; k++) gw[k] = ((const ull*)GW2)[k];
    #define WK(k) gw[(k) <= 5 ? (k) : 10 - (k)]

    // ---- zero guard rows 64,65 of h buffer ----
    if (tid < 2 * HSTR) h[LH * HSTR + tid] = 0ull;

    // ---- horizontal pass: 1 group of 8 outputs per thread ----
    float mse_acc = 0.f;
    {
        const int r   = tid >> 2;          // 0..63
        const int cg  = (tid & 3) << 3;    // 0,8,16,24
        const int gr  = r0 + r;
        const bool rowok = ((unsigned)gr < IMG);
        const int start = base + cg - 8;
        const bool mrowok = rowok & (r >= HALO) & (r < HALO + TH);

        const float* xrow = xp + gr * IMG;
        const float* yrow = yp + gr * IMG;

        float fx[24], fy[24];
        #pragma unroll
        for (int q = 0; q < 6; q++) {
            const int col = start + 4 * q;
            float4 a = make_float4(0.f, 0.f, 0.f, 0.f);
            float4 b = make_float4(0.f, 0.f, 0.f, 0.f);
            if (rowok & ((unsigned)col < IMG)) {
                a = __ldg((const float4*)(xrow + col));
                b = __ldg((const float4*)(yrow + col));
            }
            fx[4*q+0] = a.x; fx[4*q+1] = a.y; fx[4*q+2] = a.z; fx[4*q+3] = a.w;
            fy[4*q+0] = b.x; fy[4*q+1] = b.y; fy[4*q+2] = b.z; fy[4*q+3] = b.w;
        }

        ull a1[8] = {0,0,0,0,0,0,0,0};
        ull a2[8] = {0,0,0,0,0,0,0,0};
        #pragma unroll
        for (int t = 0; t < 18; t++) {
            const int vi = t + 3;                 // column = base+cg+t-5
            float s = fx[vi] + fy[vi];
            float d = fx[vi] - fy[vi];
            if (t >= 5 && t <= 12) {              // central 8 cols -> MSE
                if (mrowok) mse_acc = fmaf(d, d, mse_acc);
            }
            ull v  = pack2(s, d);
            ull v2 = mul2(v, v);
            #pragma unroll
            for (int o = 0; o < 8; o++) {
                const int k = t - o;
                if (k >= 0 && k <= 10) {
                    a1[o] = fma2(v,  WK(k), a1[o]);
                    a2[o] = fma2(v2, WK(k), a2[o]);
                }
            }
        }
        ull* hrow = h + r * HSTR;
        #pragma unroll
        for (int o = 0; o < 8; o++) {
            *((ulonglong2*)(hrow + 2 * (cg + o))) = make_ulonglong2(a1[o], a2[o]);
        }
    }
    __syncthreads();

    // ---- vertical pass: 1 column x 7 consecutive rows per thread ----
    const int c  = tid & 31;
    const int rb = (tid >> 5) * 7;     // 0,7,...,49

    ull b1[7] = {0,0,0,0,0,0,0};
    ull b2[7] = {0,0,0,0,0,0,0};
    const ull* vp = h + rb * HSTR + 2 * c;
    #pragma unroll
    for (int j = 0; j < 17; j++) {
        ulonglong2 u = *((const ulonglong2*)(vp + j * HSTR));
        #pragma unroll
        for (int o = 0; o < 7; o++) {
            const int k = j - o;
            if (k >= 0 && k <= 10) {
                b1[o] = fma2(u.x, WK(k), b1[o]);
                b2[o] = fma2(u.y, WK(k), b2[o]);
            }
        }
    }

    float ssim_acc = 0.f;
    #pragma unroll
    for (int o = 0; o < 7; o++) {
        const int tr  = rb + o;                       // tile output row
        const int gro = by * TH + tr;                 // global output row
        if (tr < TH && gro < IMG) {
            float2 m = unpack2(b1[o]);   // (mu_s, mu_d)
            float2 e = unpack2(b2[o]);   // (E[s^2], E[d^2])
            float mus2 = m.x * m.x;
            float mud2 = m.y * m.y;
            float mu12   = 0.25f * (mus2 - mud2);
            float musum  = 0.5f  * (mus2 + mud2);
            float sig12  = 0.25f * (e.x - e.y) - mu12;
            float sigsum = 0.5f  * (e.x + e.y) - musum;
            float num = (2.f * mu12 + C1f) * (2.f * sig12 + C2f);
            float den = (musum + C1f) * (sigsum + C2f);
            ssim_acc += __fdividef(num, den);
        }
    }

    // ---- block reduction -> deterministic fixed-point atomics ----
    #pragma unroll
    for (int off = 16; off > 0; off >>= 1) {
        ssim_acc += __shfl_down_sync(0xffffffffu, ssim_acc, off);
        mse_acc  += __shfl_down_sync(0xffffffffu, mse_acc,  off);
    }
    if ((tid & 31) == 0) {
        red[tid >> 5]       = ssim_acc;
        red[8 + (tid >> 5)] = mse_acc;
    }
    __syncthreads();
    if (tid == 0) {
        float ss = 0.f, mm = 0.f;
        #pragma unroll
        for (int w = 0; w < 8; w++) { ss += red[w]; mm += red[8 + w]; }
        atomicAdd(&g_acc[0], (ull)__double2ll_rn((double)ss * FXS));
        atomicAdd(&g_acc[1], (ull)__double2ll_rn((double)mm * FXS));
        __threadfence();
        unsigned t = atomicAdd(&g_count, 1u);
        s_last = (t == NBLOCKS - 1);
    }
    __syncthreads();

    // ---- last block finalizes and resets for next graph replay ----
    if (s_last && tid == 0) {
        __threadfence();
        ull a0  = atomicExch(&g_acc[0], 0ull);
        ull a1v = atomicExch(&g_acc[1], 0ull);
        atomicExch(&g_count, 0u);
        double inv = 1.0 / (NPIX * FXS);
        double ss = (double)(long long)a0 * inv;
        double mm = (double)(long long)a1v * inv;
        out[0] = (float)(1.0 - ss + mm);
    }
}

extern "C" void kernel_launch(void* const* d_in, const int* in_sizes, int n_in,
                              void* d_out, int out_size)
{
    const float* x = (const float*)d_in[0];
    const float* y = (const float*)d_in[1];
    float* out = (float*)d_out;

    dim3 grid(NBX, NBY, NPL);   // (16, 10, 48) = 7680 blocks
    loss_kernel<<<grid, 256>>>(x, y, out);
}

// round 5
// speedup vs baseline: 1.6522x; 1.0306x over previous
#include <cuda_runtime.h>

// ---------------------------------------------------------------------------
// RestorationLoss: 1 - SSIM(x,y) + MSE(x,y), single fused kernel.
//   * separable 11-tap Gaussian; packed f32x2 fields (s,d),(s^2,d^2) (FFMA2)
//   * h-pass: 8 outputs/thread, 4 own float4 loads + shfl for window endpoints
//   * v-pass: 11 outputs/thread (21/11 re-read ratio)
//   * deterministic fixed-point atomic reduction + last-block finalize/reset
// ---------------------------------------------------------------------------

#define IMG     512
#define TW      32
#define TH      88
#define HALO    5
#define LH      98                 // TH + 2*HALO
#define HSTR    66                 // ull row stride (32 interleaved pairs + pad)
#define HUNITS  (LH*4)             // 392 h-pass work units
#define NBX     (IMG/TW)           // 16
#define NBY     6                  // ceil(512/88)
#define NPL     48
#define NBLOCKS (NBX*NBY*NPL)      // 4608
#define NPIX    (16.0*3.0*512.0*512.0)
#define FXS     268435456.0        // 2^28

#define C1f 1.0e-4f
#define C2f 9.0e-4f

typedef unsigned long long ull;

__constant__ float2 GW2[6] = {
    {0.00102838f, 0.00102838f},
    {0.00759876f, 0.00759876f},
    {0.03600077f, 0.03600077f},
    {0.10936069f, 0.10936069f},
    {0.21300554f, 0.21300554f},
    {0.26601172f, 0.26601172f}
};

__device__ ull g_acc[2] = {0ull, 0ull};
__device__ unsigned g_count = 0u;

static __device__ __forceinline__ ull fma2(ull a, ull b, ull c) {
    ull r; asm("fma.rn.f32x2 %0, %1, %2, %3;" : "=l"(r) : "l"(a), "l"(b), "l"(c));
    return r;
}
static __device__ __forceinline__ ull mul2(ull a, ull b) {
    ull r; asm("mul.rn.f32x2 %0, %1, %2;" : "=l"(r) : "l"(a), "l"(b));
    return r;
}
static __device__ __forceinline__ ull pack2(float lo, float hi) {
    ull r; asm("mov.b64 %0, {%1,%2};" : "=l"(r) : "f"(lo), "f"(hi));
    return r;
}
static __device__ __forceinline__ float2 unpack2(ull v) {
    float2 r; asm("mov.b64 {%0,%1}, %2;" : "=f"(r.x), "=f"(r.y) : "l"(v));
    return r;
}

__global__ __launch_bounds__(256, 3)
void loss_kernel(const float* __restrict__ x, const float* __restrict__ y,
                 float* __restrict__ out)
{
    __shared__ ull  h[LH * HSTR];      // interleaved (h1,h2): col c -> 2c, 2c+1
    __shared__ float red[16];
    __shared__ int  s_last;

    const int tid   = threadIdx.x;
    const int bx    = blockIdx.x;
    const int by    = blockIdx.y;
    const int plane = blockIdx.z;
    const int base  = bx * TW;
    const int r0    = by * TH - HALO;

    const float* __restrict__ xp = x + (size_t)plane * (IMG * IMG);
    const float* __restrict__ yp = y + (size_t)plane * (IMG * IMG);

    ull gw[6];
    #pragma unroll
    for (int k = 0; k < 6; k++) gw[k] = ((const ull*)GW2)[k];
    #define WK(k) gw[(k) <= 5 ? (k) : 10 - (k)]

    // ---- horizontal pass: 8 outputs/unit, window endpoints via shfl ----
    ull mse2 = 0ull;                  // packed (junk, sum d^2)
    for (int iter = 0; iter < 2; iter++) {
        const int u     = iter * 256 + tid;
        const bool valid = (u < HUNITS);
        const int uu    = valid ? u : (HUNITS - 1);
        const int r     = uu >> 2;
        const int q     = uu & 3;          // == tid&3 for valid units
        const int gr    = r0 + r;
        const bool rowok = ((unsigned)gr < IMG);
        const int c0c   = base + 8 * q;    // own first output col
        const float* xrow = xp + gr * IMG;
        const float* yrow = yp + gr * IMG;

        // own + adjacent loads: cols [c0c-4, c0c+12)
        float4 X[4], Y[4];
        #pragma unroll
        for (int m = 0; m < 4; m++) {
            const int col = c0c - 4 + 4 * m;
            const bool ok = rowok & ((unsigned)col < IMG);
            X[m] = ok ? __ldg((const float4*)(xrow + col)) : make_float4(0.f,0.f,0.f,0.f);
            Y[m] = ok ? __ldg((const float4*)(yrow + col)) : make_float4(0.f,0.f,0.f,0.f);
        }
        // edge-quad extras
        float ex = 0.f, ey = 0.f, fxe = 0.f, fye = 0.f;
        if (q == 0) {
            const int col = base - 8;
            if (rowok & (col >= 0)) {
                ex = __ldg((const float4*)(xrow + col)).w;
                ey = __ldg((const float4*)(yrow + col)).w;
            }
        }
        if (q == 3) {
            const int col = c0c + 12;
            if (rowok & ((unsigned)col < IMG)) {
                fxe = __ldg((const float4*)(xrow + col)).x;
                fye = __ldg((const float4*)(yrow + col)).x;
            }
        }

        // window w[0..17] <-> cols c0c-5 .. c0c+12, packed (s,d)
        ull w[18];
        #pragma unroll
        for (int m = 0; m < 4; m++) {
            const float* fxp = (const float*)&X[m];
            const float* fyp = (const float*)&Y[m];
            #pragma unroll
            for (int e = 0; e < 4; e++)
                w[1 + 4*m + e] = pack2(fxp[e] + fyp[e], fxp[e] - fyp[e]);
        }
        ull wl = __shfl_up_sync(0xffffffffu, w[8], 1);   // lane-1 col c0c-5
        ull wr = __shfl_down_sync(0xffffffffu, w[9], 1); // lane+1 col c0c+12
        if (q == 0) wl = pack2(ex + ey, ex - ey);
        if (q == 3) wr = pack2(fxe + fye, fxe - fye);
        w[0]  = wl;
        w[17] = wr;

        const bool mrowok = valid & (r >= HALO) & (r < HALO + TH) & (gr < IMG);

        ull a1[8] = {0,0,0,0,0,0,0,0};
        ull a2[8] = {0,0,0,0,0,0,0,0};
        #pragma unroll
        for (int t = 0; t < 18; t++) {
            ull v  = w[t];
            ull v2 = mul2(v, v);
            if (t >= 5 && t <= 12) {
                if (mrowok) mse2 = fma2(v, v, mse2);
            }
            #pragma unroll
            for (int o = 0; o < 8; o++) {
                const int k = t - o;
                if (k >= 0 && k <= 10) {
                    a1[o] = fma2(v,  WK(k), a1[o]);
                    a2[o] = fma2(v2, WK(k), a2[o]);
                }
            }
        }
        if (valid) {
            ull* hrow = h + r * HSTR;
            #pragma unroll
            for (int o = 0; o < 8; o++)
                *((ulonglong2*)(hrow + 2 * (8*q + o))) = make_ulonglong2(a1[o], a2[o]);
        }
    }
    float mse_acc = unpack2(mse2).y;
    __syncthreads();

    // ---- vertical pass: 1 column x 11 consecutive rows per thread ----
    const int c  = tid & 31;
    const int rb = (tid >> 5) * 11;    // 0,11,...,77

    ull b1[11] = {0,0,0,0,0,0,0,0,0,0,0};
    ull b2[11] = {0,0,0,0,0,0,0,0,0,0,0};
    const ull* vp = h + rb * HSTR + 2 * c;
    #pragma unroll
    for (int j = 0; j < 21; j++) {
        ulonglong2 u = *((const ulonglong2*)(vp + j * HSTR));
        #pragma unroll
        for (int o = 0; o < 11; o++) {
            const int k = j - o;
            if (k >= 0 && k <= 10) {
                b1[o] = fma2(u.x, WK(k), b1[o]);
                b2[o] = fma2(u.y, WK(k), b2[o]);
            }
        }
    }

    float ssim_acc = 0.f;
    #pragma unroll
    for (int o = 0; o < 11; o++) {
        const int gro = by * TH + rb + o;
        if (gro < IMG) {
            float2 m = unpack2(b1[o]);   // (mu_s, mu_d)
            float2 e = unpack2(b2[o]);   // (E[s^2], E[d^2])
            float mus2 = m.x * m.x;
            float mud2 = m.y * m.y;
            float mu12   = 0.25f * (mus2 - mud2);
            float musum  = 0.5f  * (mus2 + mud2);
            float sig12  = 0.25f * (e.x - e.y) - mu12;
            float sigsum = 0.5f  * (e.x + e.y) - musum;
            float num = (2.f * mu12 + C1f) * (2.f * sig12 + C2f);
            float den = (musum + C1f) * (sigsum + C2f);
            ssim_acc += __fdividef(num, den);
        }
    }

    // ---- block reduction -> deterministic fixed-point atomics ----
    #pragma unroll
    for (int off = 16; off > 0; off >>= 1) {
        ssim_acc += __shfl_down_sync(0xffffffffu, ssim_acc, off);
        mse_acc  += __shfl_down_sync(0xffffffffu, mse_acc,  off);
    }
    if ((tid & 31) == 0) {
        red[tid >> 5]       = ssim_acc;
        red[8 + (tid >> 5)] = mse_acc;
    }
    __syncthreads();
    if (tid == 0) {
        float ss = 0.f, mm = 0.f;
        #pragma unroll
        for (int w2 = 0; w2 < 8; w2++) { ss += red[w2]; mm += red[8 + w2]; }
        atomicAdd(&g_acc[0], (ull)__double2ll_rn((double)ss * FXS));
        atomicAdd(&g_acc[1], (ull)__double2ll_rn((double)mm * FXS));
        __threadfence();
        unsigned t = atomicAdd(&g_count, 1u);
        s_last = (t == NBLOCKS - 1);
    }
    __syncthreads();

    // ---- last block finalizes and resets for next graph replay ----
    if (s_last && tid == 0) {
        __threadfence();
        ull a0  = atomicExch(&g_acc[0], 0ull);
        ull a1v = atomicExch(&g_acc[1], 0ull);
        atomicExch(&g_count, 0u);
        double inv = 1.0 / (NPIX * FXS);
        double ss = (double)(long long)a0 * inv;
        double mm = (double)(long long)a1v * inv;
        out[0] = (float)(1.0 - ss + mm);
    }
}

extern "C" void kernel_launch(void* const* d_in, const int* in_sizes, int n_in,
                              void* d_out, int out_size)
{
    const float* x = (const float*)d_in[0];
    const float* y = (const float*)d_in[1];
    float* out = (float*)d_out;

    dim3 grid(NBX, NBY, NPL);   // (16, 6, 48) = 4608 blocks
    loss_kernel<<<grid, 256>>>(x, y, out);
}